// round 9
// baseline (speedup 1.0000x reference)
#include <cuda_runtime.h>
#include <cuda_fp16.h>
#include <math.h>
#include <stdint.h>

#define DIM     1024
#define TLEN    16384
#define WIN     32
#define DH      64
#define HEADS   16
#define NWIN    (TLEN / WIN)      // 512
#define QKV_N   (3 * DIM)         // 3072

// ---------------- scratch (static device globals; no allocation) ----------------
static __device__ __half g_normed[(size_t)TLEN * DIM];   // (T, C) fp16
static __device__ __half g_qkv[(size_t)TLEN * QKV_N];    // (T, 3C) fp16
static __device__ __half g_attn[(size_t)TLEN * DIM];     // (T, C) fp16
static __device__ __half g_wqkv_h[(size_t)QKV_N * DIM];  // fp16 weights
static __device__ __half g_wout_h[(size_t)DIM * DIM];    // fp16 weights
static __device__ float  g_rope_cos[WIN * 32];
static __device__ float  g_rope_sin[WIN * 32];

// =============================== helpers ===================================
__device__ __forceinline__ uint32_t smem_u32(const void* p) {
    uint32_t a;
    asm("{ .reg .u64 t; cvta.to.shared.u64 t, %1; cvt.u32.u64 %0, t; }" : "=r"(a) : "l"(p));
    return a;
}
__device__ __forceinline__ float rna_tf32(float x) {
    uint32_t r;
    asm("cvt.rna.tf32.f32 %0, %1;" : "=r"(r) : "f"(x));
    return __uint_as_float(r);
}
#define LDMATRIX_X4(r0, r1, r2, r3, addr) \
    asm volatile("ldmatrix.sync.aligned.m8n8.x4.shared.b16 {%0,%1,%2,%3}, [%4];" \
                 : "=r"(r0), "=r"(r1), "=r"(r2), "=r"(r3) : "r"(addr))

// =================================================================================
// Kernel 0a: round fp32 -> fp16 weights
// =================================================================================
__global__ void round_fp16_kernel(const float* __restrict__ in, __half* __restrict__ out, int n4)
{
    int i = blockIdx.x * blockDim.x + threadIdx.x;
    if (i < n4) {
        float4 v = *(const float4*)&in[i * 4];
        *(__half2*)&out[i * 4]     = __floats2half2_rn(v.x, v.y);
        *(__half2*)&out[i * 4 + 2] = __floats2half2_rn(v.z, v.w);
    }
}

// =================================================================================
// Kernel 0b: RoPE table init
// =================================================================================
__global__ void rope_init_kernel()
{
    int idx = threadIdx.x;
    int n = idx >> 5;
    int i = idx & 31;
    float invf = expf(-logf(10000.f) * (float)i * (1.0f / 32.0f));
    float ang  = (float)n * invf;
    g_rope_cos[idx] = cosf(ang);
    g_rope_sin[idx] = sinf(ang);
}

// =================================================================================
// Kernel 1: LayerNorm over channels + transpose (C,T) -> (T,C), fp16 output.
// =================================================================================
#define LN_STRIDE 1026
#define LN_SMEM_BYTES (32 * LN_STRIDE * 2)   // 65664

__global__ void __launch_bounds__(1024) ln_transpose_kernel(
    const float* __restrict__ x,
    const float* __restrict__ gamma,
    const float* __restrict__ beta)
{
    extern __shared__ __half st[];
    __shared__ float reds[32][33];
    __shared__ float redq[32][33];
    __shared__ float s_mean[32], s_rstd[32];

    const int tx = threadIdx.x;
    const int ty = threadIdx.y;
    const int t0 = blockIdx.x * 32;
    const int tid = ty * 32 + tx;

    float cache[32];
    float sum = 0.f, sumsq = 0.f;
    #pragma unroll
    for (int ci = 0; ci < 32; ci++) {
        float v = x[(size_t)(ci * 32 + ty) * TLEN + t0 + tx];
        cache[ci] = v;
        sum += v;
        sumsq += v * v;
    }
    reds[ty][tx] = sum;
    redq[ty][tx] = sumsq;
    __syncthreads();
    for (int s = 16; s > 0; s >>= 1) {
        if (ty < s) {
            reds[ty][tx] += reds[ty + s][tx];
            redq[ty][tx] += redq[ty + s][tx];
        }
        __syncthreads();
    }
    if (ty == 0) {
        float m = reds[0][tx] * (1.0f / DIM);
        float var = redq[0][tx] * (1.0f / DIM) - m * m;
        s_mean[tx] = m;
        s_rstd[tx] = rsqrtf(var + 1e-5f);
    }
    __syncthreads();

    const float mean = s_mean[tx];
    const float rstd = s_rstd[tx];
    #pragma unroll
    for (int ci = 0; ci < 32; ci++) {
        int c = ci * 32 + ty;
        float nv = (cache[ci] - mean) * rstd * gamma[c] + beta[c];
        st[tx * LN_STRIDE + c] = __float2half_rn(nv);
    }
    __syncthreads();

    const uint32_t stb = smem_u32(st);
    #pragma unroll
    for (int i = 0; i < 4; i++) {
        int idx = tid + i * 1024;
        int tok = idx >> 7;
        int f4  = idx & 127;
        uint32_t sa = stb + (uint32_t)(tok * LN_STRIDE + f4 * 8) * 2;
        uint4 u;
        asm volatile("ld.shared.u32 %0, [%1];"      : "=r"(u.x) : "r"(sa));
        asm volatile("ld.shared.u32 %0, [%1 + 4];"  : "=r"(u.y) : "r"(sa));
        asm volatile("ld.shared.u32 %0, [%1 + 8];"  : "=r"(u.z) : "r"(sa));
        asm volatile("ld.shared.u32 %0, [%1 + 12];" : "=r"(u.w) : "r"(sa));
        *(uint4*)&g_normed[(size_t)(t0 + tok) * DIM + f4 * 8] = u;
    }
}

// =================================================================================
// Kernel 2: fp16 mma.sync GEMM-NT, 128 threads, 4 warps of 64x64 (less smem traffic).
// C[M,N] = A[M,K] * B[N,K]^T (+resid). BM=BN=128, BK=64, 3-stage cp.async.
// =================================================================================
#define GBM 128
#define GBN 128
#define GBK 64
#define GSTAGES 3
#define ROWH 72
#define TILEH (128 * ROWH)
#define STAGEH (2 * TILEH)
#define GSMEM_BYTES (GSTAGES * STAGEH * 2)   // 110592 B

template <bool RESID, typename TOUT>
__global__ void __launch_bounds__(128) hgemm_nt(
    const __half* __restrict__ A,
    const __half* __restrict__ B,
    TOUT* __restrict__ C,
    const float* __restrict__ resid,
    int M, int N, int K)
{
    extern __shared__ __half sh[];
    const uint32_t shb = smem_u32(sh);
    const int tid  = threadIdx.x;
    const int wid  = tid >> 5;
    const int lane = tid & 31;
    const int g = lane >> 2;
    const int t = lane & 3;
    const int m0 = blockIdx.y * GBM;
    const int n0 = blockIdx.x * GBN;
    const int wm = (wid >> 1) * 64;        // warp m offset (0 or 64)
    const int wn = (wid & 1) * 64;         // warp n offset (0 or 64)
    const int KC = K / GBK;

    // ldmatrix per-lane address components (same validated mapping as before)
    const int a_row = wm + (lane & 15);
    const int a_col = (lane >> 4) << 3;
    const int b_row = wn + ((lane >> 4) << 3) + (lane & 7);
    const int b_col = ((lane >> 3) & 1) << 3;
    const uint32_t a_off = (uint32_t)(a_row * ROWH + a_col) * 2;
    const uint32_t b_off = (uint32_t)(TILEH + b_row * ROWH + b_col) * 2;

    float c[4][8][4];
    #pragma unroll
    for (int mi = 0; mi < 4; mi++)
        #pragma unroll
        for (int ni = 0; ni < 8; ni++)
            #pragma unroll
            for (int j = 0; j < 4; j++) c[mi][ni][j] = 0.f;

    // loader: 128 threads, per tile 128 rows x 8 chunks(16B); 8 iters per tile
    const int lrow = tid >> 3;                // 0..15
    const int lc8  = (tid & 7) << 3;          // half offset 0..56

    #pragma unroll
    for (int s = 0; s < GSTAGES - 1; s++) {
        __half* as = sh + s * STAGEH;
        __half* bs = as + TILEH;
        #pragma unroll
        for (int i = 0; i < 8; i++) {
            int row = lrow + i * 16;
            uint32_t sa = smem_u32(as + row * ROWH + lc8);
            const __half* ga = A + (size_t)(m0 + row) * K + s * GBK + lc8;
            asm volatile("cp.async.cg.shared.global [%0], [%1], 16;" :: "r"(sa), "l"(ga));
            uint32_t sb = smem_u32(bs + row * ROWH + lc8);
            const __half* gb = B + (size_t)(n0 + row) * K + s * GBK + lc8;
            asm volatile("cp.async.cg.shared.global [%0], [%1], 16;" :: "r"(sb), "l"(gb));
        }
        asm volatile("cp.async.commit_group;");
    }

    for (int kc = 0; kc < KC; kc++) {
        if (kc + 1 < KC) asm volatile("cp.async.wait_group 1;");
        else             asm volatile("cp.async.wait_group 0;");
        __syncthreads();

        int nxt = kc + 2;
        if (nxt < KC) {
            int slot = nxt % GSTAGES;
            __half* as = sh + slot * STAGEH;
            __half* bs = as + TILEH;
            #pragma unroll
            for (int i = 0; i < 8; i++) {
                int row = lrow + i * 16;
                uint32_t sa = smem_u32(as + row * ROWH + lc8);
                const __half* ga = A + (size_t)(m0 + row) * K + nxt * GBK + lc8;
                asm volatile("cp.async.cg.shared.global [%0], [%1], 16;" :: "r"(sa), "l"(ga));
                uint32_t sb = smem_u32(bs + row * ROWH + lc8);
                const __half* gb = B + (size_t)(n0 + row) * K + nxt * GBK + lc8;
                asm volatile("cp.async.cg.shared.global [%0], [%1], 16;" :: "r"(sb), "l"(gb));
            }
            asm volatile("cp.async.commit_group;");
        }

        const uint32_t stg = shb + (uint32_t)((kc % GSTAGES) * STAGEH) * 2;
        const uint32_t abase = stg + a_off;
        const uint32_t bbase = stg + b_off;

        #pragma unroll
        for (int kk = 0; kk < GBK; kk += 16) {
            uint32_t a[4][4], b[8][2];
            #pragma unroll
            for (int mi = 0; mi < 4; mi++) {
                uint32_t aa = abase + (uint32_t)(mi * 16 * ROWH + kk) * 2;
                LDMATRIX_X4(a[mi][0], a[mi][1], a[mi][2], a[mi][3], aa);
            }
            #pragma unroll
            for (int np = 0; np < 4; np++) {
                uint32_t bb = bbase + (uint32_t)(np * 16 * ROWH + kk) * 2;
                LDMATRIX_X4(b[2 * np][0], b[2 * np][1], b[2 * np + 1][0], b[2 * np + 1][1], bb);
            }
            #pragma unroll
            for (int mi = 0; mi < 4; mi++)
                #pragma unroll
                for (int ni = 0; ni < 8; ni++)
                    asm volatile(
                        "mma.sync.aligned.m16n8k16.row.col.f32.f16.f16.f32 "
                        "{%0,%1,%2,%3},{%4,%5,%6,%7},{%8,%9},{%0,%1,%2,%3};"
                        : "+f"(c[mi][ni][0]), "+f"(c[mi][ni][1]),
                          "+f"(c[mi][ni][2]), "+f"(c[mi][ni][3])
                        : "r"(a[mi][0]), "r"(a[mi][1]), "r"(a[mi][2]), "r"(a[mi][3]),
                          "r"(b[ni][0]), "r"(b[ni][1]));
        }
    }

    // epilogue: thread (g,t) owns rows (wm+16mi+g, +8), cols (wn+8ni+2t, +1)
    #pragma unroll
    for (int mi = 0; mi < 4; mi++) {
        #pragma unroll
        for (int ni = 0; ni < 8; ni++) {
            size_t r0  = (size_t)(m0 + wm + mi * 16 + g);
            size_t col = (size_t)(n0 + wn + ni * 8 + 2 * t);
            size_t off0 = r0 * N + col;
            size_t off1 = (r0 + 8) * N + col;
            if constexpr (RESID) {
                float2 rv0 = *(const float2*)&resid[off0];
                float2 rv1 = *(const float2*)&resid[off1];
                float2 v0 = make_float2(c[mi][ni][0] + rv0.x, c[mi][ni][1] + rv0.y);
                float2 v1 = make_float2(c[mi][ni][2] + rv1.x, c[mi][ni][3] + rv1.y);
                *(float2*)&((float*)C)[off0] = v0;
                *(float2*)&((float*)C)[off1] = v1;
            } else {
                *(__half2*)&((__half*)C)[off0] = __floats2half2_rn(c[mi][ni][0], c[mi][ni][1]);
                *(__half2*)&((__half*)C)[off1] = __floats2half2_rn(c[mi][ni][2], c[mi][ni][3]);
            }
        }
    }
}

// =================================================================================
// Kernel 3: warp-per-(window,head) attention via tf32 mma.sync, fp16 in/out.
// =================================================================================
#define AWARPS 4
#define ASTRIDE 68
#define AWARP_F (3 * 32 * ASTRIDE)
#define ASMEM_BYTES (AWARPS * AWARP_F * 4)   // 104448 B

__device__ __forceinline__ void h8_to_f8(uint4 u, float* dst) {
    const __half2* hp = (const __half2*)&u;
    #pragma unroll
    for (int j = 0; j < 4; j++) {
        float2 f = __half22float2(hp[j]);
        dst[2 * j]     = f.x;
        dst[2 * j + 1] = f.y;
    }
}

__global__ void __launch_bounds__(AWARPS * 32) attn_mma_kernel()
{
    extern __shared__ float as_[];
    const int lane = threadIdx.x & 31;
    const int wid  = threadIdx.x >> 5;
    const int pair = blockIdx.x * AWARPS + wid;
    const int w = pair >> 4;
    const int h = pair & 15;
    const int gr = lane >> 2;
    const int t  = lane & 3;

    float* q = as_ + wid * AWARP_F;
    float* k = q + 32 * ASTRIDE;
    float* v = k + 32 * ASTRIDE;
    float* p = q;

    const __half* gbase = g_qkv + (size_t)w * WIN * QKV_N + h * DH;

    #pragma unroll
    for (int it = 0; it < 8; it++) {
        int idx = lane + it * 32;
        int n   = idx >> 3;
        int d8  = (idx & 7) << 3;
        const __half* rp = gbase + (size_t)n * QKV_N + d8;
        uint4 qa = *(const uint4*)rp;
        uint4 ka = *(const uint4*)(rp + DIM);
        uint4 va = *(const uint4*)(rp + 2 * DIM);
        h8_to_f8(qa, q + n * ASTRIDE + d8);
        h8_to_f8(ka, k + n * ASTRIDE + d8);
        h8_to_f8(va, v + n * ASTRIDE + d8);
    }
    __syncwarp();

    #pragma unroll
    for (int it = 0; it < 32; it++) {
        int idx = lane + it * 32;
        int n = idx >> 5;
        int i = idx & 31;
        float c = g_rope_cos[idx];
        float s = g_rope_sin[idx];
        float* qr = q + n * ASTRIDE;
        float* kr = k + n * ASTRIDE;
        float qa = qr[i], qb = qr[i + 32];
        qr[i]      = rna_tf32(qa * c - qb * s);
        qr[i + 32] = rna_tf32(qb * c + qa * s);
        float ka = kr[i], kb = kr[i + 32];
        kr[i]      = rna_tf32(ka * c - kb * s);
        kr[i + 32] = rna_tf32(kb * c + ka * s);
    }
    __syncwarp();

    float s[2][4][4];
    #pragma unroll
    for (int mi = 0; mi < 2; mi++)
        #pragma unroll
        for (int nt = 0; nt < 4; nt++)
            #pragma unroll
            for (int j = 0; j < 4; j++) s[mi][nt][j] = 0.f;

    #pragma unroll
    for (int kk = 0; kk < 64; kk += 8) {
        uint32_t a[2][4], b[4][2];
        #pragma unroll
        for (int mi = 0; mi < 2; mi++) {
            const float* ap = q + (mi * 16 + gr) * ASTRIDE + kk + t;
            a[mi][0] = __float_as_uint(ap[0]);
            a[mi][1] = __float_as_uint(ap[8 * ASTRIDE]);
            a[mi][2] = __float_as_uint(ap[4]);
            a[mi][3] = __float_as_uint(ap[8 * ASTRIDE + 4]);
        }
        #pragma unroll
        for (int nt = 0; nt < 4; nt++) {
            const float* bp = k + (nt * 8 + gr) * ASTRIDE + kk + t;
            b[nt][0] = __float_as_uint(bp[0]);
            b[nt][1] = __float_as_uint(bp[4]);
        }
        #pragma unroll
        for (int mi = 0; mi < 2; mi++)
            #pragma unroll
            for (int nt = 0; nt < 4; nt++)
                asm volatile(
                    "mma.sync.aligned.m16n8k8.row.col.f32.tf32.tf32.f32 "
                    "{%0,%1,%2,%3},{%4,%5,%6,%7},{%8,%9},{%0,%1,%2,%3};"
                    : "+f"(s[mi][nt][0]), "+f"(s[mi][nt][1]),
                      "+f"(s[mi][nt][2]), "+f"(s[mi][nt][3])
                    : "r"(a[mi][0]), "r"(a[mi][1]), "r"(a[mi][2]), "r"(a[mi][3]),
                      "r"(b[nt][0]), "r"(b[nt][1]));
    }
    __syncwarp();

    const float scale = 0.125f;
    #pragma unroll
    for (int mi = 0; mi < 2; mi++) {
        #pragma unroll
        for (int half = 0; half < 2; half++) {
            int row = mi * 16 + gr + 8 * half;
            float e[8];
            float m = -1e30f;
            #pragma unroll
            for (int nt = 0; nt < 4; nt++) {
                e[2 * nt]     = s[mi][nt][2 * half]     * scale;
                e[2 * nt + 1] = s[mi][nt][2 * half + 1] * scale;
                m = fmaxf(m, fmaxf(e[2 * nt], e[2 * nt + 1]));
            }
            m = fmaxf(m, __shfl_xor_sync(0xFFFFFFFFu, m, 1));
            m = fmaxf(m, __shfl_xor_sync(0xFFFFFFFFu, m, 2));
            float sum = 0.f;
            #pragma unroll
            for (int j = 0; j < 8; j++) {
                e[j] = __expf(e[j] - m);
                sum += e[j];
            }
            sum += __shfl_xor_sync(0xFFFFFFFFu, sum, 1);
            sum += __shfl_xor_sync(0xFFFFFFFFu, sum, 2);
            float inv = __fdividef(1.0f, sum);
            float* pr = p + row * ASTRIDE + 2 * t;
            #pragma unroll
            for (int nt = 0; nt < 4; nt++) {
                pr[nt * 8]     = rna_tf32(e[2 * nt]     * inv);
                pr[nt * 8 + 1] = rna_tf32(e[2 * nt + 1] * inv);
            }
        }
    }
    __syncwarp();

    float o[2][8][4];
    #pragma unroll
    for (int mi = 0; mi < 2; mi++)
        #pragma unroll
        for (int nt = 0; nt < 8; nt++)
            #pragma unroll
            for (int j = 0; j < 4; j++) o[mi][nt][j] = 0.f;

    #pragma unroll
    for (int kk = 0; kk < 32; kk += 8) {
        uint32_t a[2][4];
        #pragma unroll
        for (int mi = 0; mi < 2; mi++) {
            const float* ap = p + (mi * 16 + gr) * ASTRIDE + kk + t;
            a[mi][0] = __float_as_uint(ap[0]);
            a[mi][1] = __float_as_uint(ap[8 * ASTRIDE]);
            a[mi][2] = __float_as_uint(ap[4]);
            a[mi][3] = __float_as_uint(ap[8 * ASTRIDE + 4]);
        }
        #pragma unroll
        for (int nt = 0; nt < 8; nt++) {
            uint32_t b0 = __float_as_uint(v[(kk + t) * ASTRIDE + nt * 8 + gr]);
            uint32_t b1 = __float_as_uint(v[(kk + t + 4) * ASTRIDE + nt * 8 + gr]);
            #pragma unroll
            for (int mi = 0; mi < 2; mi++)
                asm volatile(
                    "mma.sync.aligned.m16n8k8.row.col.f32.tf32.tf32.f32 "
                    "{%0,%1,%2,%3},{%4,%5,%6,%7},{%8,%9},{%0,%1,%2,%3};"
                    : "+f"(o[mi][nt][0]), "+f"(o[mi][nt][1]),
                      "+f"(o[mi][nt][2]), "+f"(o[mi][nt][3])
                    : "r"(a[mi][0]), "r"(a[mi][1]), "r"(a[mi][2]), "r"(a[mi][3]),
                      "r"(b0), "r"(b1));
        }
    }

    __half* op = g_attn + (size_t)(w * WIN) * DIM + h * DH;
    #pragma unroll
    for (int mi = 0; mi < 2; mi++) {
        #pragma unroll
        for (int nt = 0; nt < 8; nt++) {
            int row0 = mi * 16 + gr;
            int col  = nt * 8 + 2 * t;
            *(__half2*)&op[(size_t)row0 * DIM + col] =
                __floats2half2_rn(o[mi][nt][0], o[mi][nt][1]);
            *(__half2*)&op[(size_t)(row0 + 8) * DIM + col] =
                __floats2half2_rn(o[mi][nt][2], o[mi][nt][3]);
        }
    }
}

// =================================================================================
// launch
// =================================================================================
extern "C" void kernel_launch(void* const* d_in, const int* in_sizes, int n_in,
                              void* d_out, int out_size)
{
    (void)in_sizes; (void)n_in; (void)out_size;
    const float* x     = (const float*)d_in[0];
    const float* w_qkv = (const float*)d_in[1];
    const float* w_out = (const float*)d_in[2];
    const float* gamma = (const float*)d_in[3];
    const float* beta  = (const float*)d_in[4];
    float* out = (float*)d_out;

    __half *normed, *qkv, *attn, *wqkv_h, *wout_h;
    cudaGetSymbolAddress((void**)&normed, g_normed);
    cudaGetSymbolAddress((void**)&qkv,    g_qkv);
    cudaGetSymbolAddress((void**)&attn,   g_attn);
    cudaGetSymbolAddress((void**)&wqkv_h, g_wqkv_h);
    cudaGetSymbolAddress((void**)&wout_h, g_wout_h);

    cudaFuncSetAttribute((const void*)hgemm_nt<false, __half>,
                         cudaFuncAttributeMaxDynamicSharedMemorySize, GSMEM_BYTES);
    cudaFuncSetAttribute((const void*)hgemm_nt<true, float>,
                         cudaFuncAttributeMaxDynamicSharedMemorySize, GSMEM_BYTES);
    cudaFuncSetAttribute((const void*)attn_mma_kernel,
                         cudaFuncAttributeMaxDynamicSharedMemorySize, ASMEM_BYTES);
    cudaFuncSetAttribute((const void*)ln_transpose_kernel,
                         cudaFuncAttributeMaxDynamicSharedMemorySize, LN_SMEM_BYTES);

    // 0) round weights to fp16; init RoPE table
    round_fp16_kernel<<<(QKV_N * DIM / 4 + 255) / 256, 256>>>(w_qkv, wqkv_h, QKV_N * DIM / 4);
    round_fp16_kernel<<<(DIM * DIM / 4 + 255) / 256, 256>>>(w_out, wout_h, DIM * DIM / 4);
    rope_init_kernel<<<1, 1024>>>();

    // 1) LayerNorm + transpose -> g_normed (T, C) fp16
    ln_transpose_kernel<<<TLEN / 32, dim3(32, 32), LN_SMEM_BYTES>>>(x, gamma, beta);

    // 2) QKV GEMM (fp16 mma.sync + ldmatrix, 64x64 warp tiles)
    hgemm_nt<false, __half><<<dim3(QKV_N / GBN, TLEN / GBM), 128, GSMEM_BYTES>>>(
        normed, wqkv_h, qkv, nullptr, TLEN, QKV_N, DIM);

    // 3) windowed RoPE attention (tf32 mma.sync) -> g_attn (T, C) fp16
    attn_mma_kernel<<<NWIN * HEADS / AWARPS, AWARPS * 32, ASMEM_BYTES>>>();

    // 4) out = (w_out @ attn^T) + x, written as (C, T) fp32
    hgemm_nt<true, float><<<dim3(TLEN / GBN, DIM / GBM), 128, GSMEM_BYTES>>>(
        wout_h, attn, out, x, DIM, TLEN, DIM);
}

// round 10
// speedup vs baseline: 1.1043x; 1.1043x over previous
#include <cuda_runtime.h>
#include <cuda_fp16.h>
#include <math.h>
#include <stdint.h>

#define DIM     1024
#define TLEN    16384
#define WIN     32
#define DH      64
#define HEADS   16
#define NWIN    (TLEN / WIN)      // 512
#define QKV_N   (3 * DIM)         // 3072

// ---------------- scratch (static device globals; no allocation) ----------------
static __device__ __half g_normed[(size_t)TLEN * DIM];   // (T, C) fp16
static __device__ __half g_qkv[(size_t)TLEN * QKV_N];    // (T, 3C) fp16
static __device__ __half g_attn[(size_t)TLEN * DIM];     // (T, C) fp16
static __device__ __half g_wqkv_h[(size_t)QKV_N * DIM];  // fp16 weights
static __device__ __half g_wout_h[(size_t)DIM * DIM];    // fp16 weights
static __device__ float  g_rope_cos[WIN * 32];
static __device__ float  g_rope_sin[WIN * 32];

// =============================== helpers ===================================
__device__ __forceinline__ uint32_t smem_u32(const void* p) {
    uint32_t a;
    asm("{ .reg .u64 t; cvta.to.shared.u64 t, %1; cvt.u32.u64 %0, t; }" : "=r"(a) : "l"(p));
    return a;
}
#define LDMATRIX_X4(r0, r1, r2, r3, addr) \
    asm volatile("ldmatrix.sync.aligned.m8n8.x4.shared.b16 {%0,%1,%2,%3}, [%4];" \
                 : "=r"(r0), "=r"(r1), "=r"(r2), "=r"(r3) : "r"(addr))
#define HMMA16816(c0, c1, c2, c3, a0, a1, a2, a3, b0, b1) \
    asm volatile( \
        "mma.sync.aligned.m16n8k16.row.col.f32.f16.f16.f32 " \
        "{%0,%1,%2,%3},{%4,%5,%6,%7},{%8,%9},{%0,%1,%2,%3};" \
        : "+f"(c0), "+f"(c1), "+f"(c2), "+f"(c3) \
        : "r"(a0), "r"(a1), "r"(a2), "r"(a3), "r"(b0), "r"(b1))

// =================================================================================
// Kernel 0a: round fp32 -> fp16 weights
// =================================================================================
__global__ void round_fp16_kernel(const float* __restrict__ in, __half* __restrict__ out, int n4)
{
    int i = blockIdx.x * blockDim.x + threadIdx.x;
    if (i < n4) {
        float4 v = *(const float4*)&in[i * 4];
        *(__half2*)&out[i * 4]     = __floats2half2_rn(v.x, v.y);
        *(__half2*)&out[i * 4 + 2] = __floats2half2_rn(v.z, v.w);
    }
}

// =================================================================================
// Kernel 0b: RoPE table init
// =================================================================================
__global__ void rope_init_kernel()
{
    int idx = threadIdx.x;
    int n = idx >> 5;
    int i = idx & 31;
    float invf = expf(-logf(10000.f) * (float)i * (1.0f / 32.0f));
    float ang  = (float)n * invf;
    g_rope_cos[idx] = cosf(ang);
    g_rope_sin[idx] = sinf(ang);
}

// =================================================================================
// Kernel 1: LayerNorm over channels + transpose (C,T) -> (T,C), fp16 output.
// =================================================================================
#define LN_STRIDE 1026
#define LN_SMEM_BYTES (32 * LN_STRIDE * 2)   // 65664

__global__ void __launch_bounds__(1024) ln_transpose_kernel(
    const float* __restrict__ x,
    const float* __restrict__ gamma,
    const float* __restrict__ beta)
{
    extern __shared__ __half st[];
    __shared__ float reds[32][33];
    __shared__ float redq[32][33];
    __shared__ float s_mean[32], s_rstd[32];

    const int tx = threadIdx.x;
    const int ty = threadIdx.y;
    const int t0 = blockIdx.x * 32;
    const int tid = ty * 32 + tx;

    float cache[32];
    float sum = 0.f, sumsq = 0.f;
    #pragma unroll
    for (int ci = 0; ci < 32; ci++) {
        float v = x[(size_t)(ci * 32 + ty) * TLEN + t0 + tx];
        cache[ci] = v;
        sum += v;
        sumsq += v * v;
    }
    reds[ty][tx] = sum;
    redq[ty][tx] = sumsq;
    __syncthreads();
    for (int s = 16; s > 0; s >>= 1) {
        if (ty < s) {
            reds[ty][tx] += reds[ty + s][tx];
            redq[ty][tx] += redq[ty + s][tx];
        }
        __syncthreads();
    }
    if (ty == 0) {
        float m = reds[0][tx] * (1.0f / DIM);
        float var = redq[0][tx] * (1.0f / DIM) - m * m;
        s_mean[tx] = m;
        s_rstd[tx] = rsqrtf(var + 1e-5f);
    }
    __syncthreads();

    const float mean = s_mean[tx];
    const float rstd = s_rstd[tx];
    #pragma unroll
    for (int ci = 0; ci < 32; ci++) {
        int c = ci * 32 + ty;
        float nv = (cache[ci] - mean) * rstd * gamma[c] + beta[c];
        st[tx * LN_STRIDE + c] = __float2half_rn(nv);
    }
    __syncthreads();

    const uint32_t stb = smem_u32(st);
    #pragma unroll
    for (int i = 0; i < 4; i++) {
        int idx = tid + i * 1024;
        int tok = idx >> 7;
        int f4  = idx & 127;
        uint32_t sa = stb + (uint32_t)(tok * LN_STRIDE + f4 * 8) * 2;
        uint4 u;
        asm volatile("ld.shared.u32 %0, [%1];"      : "=r"(u.x) : "r"(sa));
        asm volatile("ld.shared.u32 %0, [%1 + 4];"  : "=r"(u.y) : "r"(sa));
        asm volatile("ld.shared.u32 %0, [%1 + 8];"  : "=r"(u.z) : "r"(sa));
        asm volatile("ld.shared.u32 %0, [%1 + 12];" : "=r"(u.w) : "r"(sa));
        *(uint4*)&g_normed[(size_t)(t0 + tok) * DIM + f4 * 8] = u;
    }
}

// =================================================================================
// Kernel 2: fp16 mma.sync GEMM-NT (R8 config: 256 threads, 8 warps of 64x32).
// C[M,N] = A[M,K] * B[N,K]^T (+resid). BM=BN=128, BK=64, 3-stage cp.async.
// =================================================================================
#define GBM 128
#define GBN 128
#define GBK 64
#define GSTAGES 3
#define ROWH 72
#define TILEH (128 * ROWH)
#define STAGEH (2 * TILEH)
#define GSMEM_BYTES (GSTAGES * STAGEH * 2)   // 110592 B

template <bool RESID, typename TOUT>
__global__ void __launch_bounds__(256) hgemm_nt(
    const __half* __restrict__ A,
    const __half* __restrict__ B,
    TOUT* __restrict__ C,
    const float* __restrict__ resid,
    int M, int N, int K)
{
    extern __shared__ __half sh[];
    const uint32_t shb = smem_u32(sh);
    const int tid  = threadIdx.x;
    const int wid  = tid >> 5;
    const int lane = tid & 31;
    const int g = lane >> 2;
    const int t = lane & 3;
    const int m0 = blockIdx.y * GBM;
    const int n0 = blockIdx.x * GBN;
    const int wm = (wid >> 2) * 64;
    const int wn = (wid & 3) * 32;
    const int KC = K / GBK;

    const int a_row = wm + (lane & 15);
    const int a_col = (lane >> 4) << 3;
    const int b_row = wn + ((lane >> 4) << 3) + (lane & 7);
    const int b_col = ((lane >> 3) & 1) << 3;
    const uint32_t a_off = (uint32_t)(a_row * ROWH + a_col) * 2;
    const uint32_t b_off = (uint32_t)(TILEH + b_row * ROWH + b_col) * 2;

    float c[4][4][4];
    #pragma unroll
    for (int mi = 0; mi < 4; mi++)
        #pragma unroll
        for (int ni = 0; ni < 4; ni++)
            #pragma unroll
            for (int j = 0; j < 4; j++) c[mi][ni][j] = 0.f;

    const int lrow = tid >> 3;
    const int lc8  = (tid & 7) << 3;

    #pragma unroll
    for (int s = 0; s < GSTAGES - 1; s++) {
        __half* as = sh + s * STAGEH;
        __half* bs = as + TILEH;
        #pragma unroll
        for (int i = 0; i < 4; i++) {
            int row = lrow + i * 32;
            uint32_t sa = smem_u32(as + row * ROWH + lc8);
            const __half* ga = A + (size_t)(m0 + row) * K + s * GBK + lc8;
            asm volatile("cp.async.cg.shared.global [%0], [%1], 16;" :: "r"(sa), "l"(ga));
            uint32_t sb = smem_u32(bs + row * ROWH + lc8);
            const __half* gb = B + (size_t)(n0 + row) * K + s * GBK + lc8;
            asm volatile("cp.async.cg.shared.global [%0], [%1], 16;" :: "r"(sb), "l"(gb));
        }
        asm volatile("cp.async.commit_group;");
    }

    for (int kc = 0; kc < KC; kc++) {
        if (kc + 1 < KC) asm volatile("cp.async.wait_group 1;");
        else             asm volatile("cp.async.wait_group 0;");
        __syncthreads();

        int nxt = kc + 2;
        if (nxt < KC) {
            int slot = nxt % GSTAGES;
            __half* as = sh + slot * STAGEH;
            __half* bs = as + TILEH;
            #pragma unroll
            for (int i = 0; i < 4; i++) {
                int row = lrow + i * 32;
                uint32_t sa = smem_u32(as + row * ROWH + lc8);
                const __half* ga = A + (size_t)(m0 + row) * K + nxt * GBK + lc8;
                asm volatile("cp.async.cg.shared.global [%0], [%1], 16;" :: "r"(sa), "l"(ga));
                uint32_t sb = smem_u32(bs + row * ROWH + lc8);
                const __half* gb = B + (size_t)(n0 + row) * K + nxt * GBK + lc8;
                asm volatile("cp.async.cg.shared.global [%0], [%1], 16;" :: "r"(sb), "l"(gb));
            }
            asm volatile("cp.async.commit_group;");
        }

        const uint32_t stg = shb + (uint32_t)((kc % GSTAGES) * STAGEH) * 2;
        const uint32_t abase = stg + a_off;
        const uint32_t bbase = stg + b_off;

        #pragma unroll
        for (int kk = 0; kk < GBK; kk += 16) {
            uint32_t a[4][4], b[4][2];
            #pragma unroll
            for (int mi = 0; mi < 4; mi++) {
                uint32_t aa = abase + (uint32_t)(mi * 16 * ROWH + kk) * 2;
                LDMATRIX_X4(a[mi][0], a[mi][1], a[mi][2], a[mi][3], aa);
            }
            #pragma unroll
            for (int np = 0; np < 2; np++) {
                uint32_t bb = bbase + (uint32_t)(np * 16 * ROWH + kk) * 2;
                LDMATRIX_X4(b[2 * np][0], b[2 * np][1], b[2 * np + 1][0], b[2 * np + 1][1], bb);
            }
            #pragma unroll
            for (int mi = 0; mi < 4; mi++)
                #pragma unroll
                for (int ni = 0; ni < 4; ni++)
                    HMMA16816(c[mi][ni][0], c[mi][ni][1], c[mi][ni][2], c[mi][ni][3],
                              a[mi][0], a[mi][1], a[mi][2], a[mi][3],
                              b[ni][0], b[ni][1]);
        }
    }

    #pragma unroll
    for (int mi = 0; mi < 4; mi++) {
        #pragma unroll
        for (int ni = 0; ni < 4; ni++) {
            size_t r0  = (size_t)(m0 + wm + mi * 16 + g);
            size_t col = (size_t)(n0 + wn + ni * 8 + 2 * t);
            size_t off0 = r0 * N + col;
            size_t off1 = (r0 + 8) * N + col;
            if constexpr (RESID) {
                float2 rv0 = *(const float2*)&resid[off0];
                float2 rv1 = *(const float2*)&resid[off1];
                float2 v0 = make_float2(c[mi][ni][0] + rv0.x, c[mi][ni][1] + rv0.y);
                float2 v1 = make_float2(c[mi][ni][2] + rv1.x, c[mi][ni][3] + rv1.y);
                *(float2*)&((float*)C)[off0] = v0;
                *(float2*)&((float*)C)[off1] = v1;
            } else {
                *(__half2*)&((__half*)C)[off0] = __floats2half2_rn(c[mi][ni][0], c[mi][ni][1]);
                *(__half2*)&((__half*)C)[off1] = __floats2half2_rn(c[mi][ni][2], c[mi][ni][3]);
            }
        }
    }
}

// =================================================================================
// Kernel 3: warp-per-(window,head) attention, FULL fp16 (m16n8k16), fp32 accum.
// Per-warp smem: q/k/v 32x72 halves (p aliases q). 55296 B per 4-warp block.
// =================================================================================
#define AWARPS 4
#define AST 72                                   // halves per row
#define AWARP_H (3 * 32 * AST)
#define ASMEM_BYTES (AWARPS * AWARP_H * 2)       // 55296 B

__global__ void __launch_bounds__(AWARPS * 32) attn_mma_kernel()
{
    extern __shared__ __half ash[];
    const int lane = threadIdx.x & 31;
    const int wid  = threadIdx.x >> 5;
    const int pair = blockIdx.x * AWARPS + wid;
    const int w = pair >> 4;
    const int h = pair & 15;
    const int gr = lane >> 2;
    const int t  = lane & 3;

    __half* q = ash + wid * AWARP_H;
    __half* k = q + 32 * AST;
    __half* v = k + 32 * AST;
    __half* p = q;                               // alias (q dead after S frags)

    const uint32_t qb_addr = smem_u32(q);
    const uint32_t kb_addr = smem_u32(k);
    const unsigned short* vs = (const unsigned short*)v;

    const __half* gbase = g_qkv + (size_t)w * WIN * QKV_N + h * DH;

    // ---- stage Q,K,V fp16 (zero-copy uint4) ----
    #pragma unroll
    for (int it = 0; it < 8; it++) {
        int idx = lane + it * 32;                // 0..255
        int n   = idx >> 3;
        int d8  = (idx & 7) << 3;
        const __half* rp = gbase + (size_t)n * QKV_N + d8;
        *(uint4*)&q[n * AST + d8] = *(const uint4*)rp;
        *(uint4*)&k[n * AST + d8] = *(const uint4*)(rp + DIM);
        *(uint4*)&v[n * AST + d8] = *(const uint4*)(rp + 2 * DIM);
    }
    __syncwarp();

    // ---- RoPE on Q,K (fp32 math, fp16 store) ----
    #pragma unroll
    for (int it = 0; it < 32; it++) {
        int idx = lane + it * 32;                // 0..1023
        int n = idx >> 5;
        int i = idx & 31;
        float c = g_rope_cos[idx];
        float s = g_rope_sin[idx];
        __half* qr = q + n * AST;
        __half* kr = k + n * AST;
        float qa = __half2float(qr[i]), qb = __half2float(qr[i + 32]);
        qr[i]      = __float2half_rn(qa * c - qb * s);
        qr[i + 32] = __float2half_rn(qb * c + qa * s);
        float ka = __half2float(kr[i]), kb = __half2float(kr[i + 32]);
        kr[i]      = __float2half_rn(ka * c - kb * s);
        kr[i + 32] = __float2half_rn(kb * c + ka * s);
    }
    __syncwarp();

    // ---- S = Q K^T : M=32, N=32, K=64 -> 4 ksteps of m16n8k16 ----
    const uint32_t a_frag_off = (uint32_t)((lane & 15) * AST + ((lane >> 4) << 3)) * 2;
    const uint32_t b_frag_off = (uint32_t)((((lane >> 4) << 3) + (lane & 7)) * AST +
                                           (((lane >> 3) & 1) << 3)) * 2;

    float sacc[2][4][4];
    #pragma unroll
    for (int mi = 0; mi < 2; mi++)
        #pragma unroll
        for (int nt = 0; nt < 4; nt++)
            #pragma unroll
            for (int j = 0; j < 4; j++) sacc[mi][nt][j] = 0.f;

    #pragma unroll
    for (int kk = 0; kk < 64; kk += 16) {
        uint32_t a[2][4], b[4][2];
        #pragma unroll
        for (int mi = 0; mi < 2; mi++) {
            uint32_t aa = qb_addr + a_frag_off + (uint32_t)(mi * 16 * AST + kk) * 2;
            LDMATRIX_X4(a[mi][0], a[mi][1], a[mi][2], a[mi][3], aa);
        }
        #pragma unroll
        for (int np = 0; np < 2; np++) {
            uint32_t bb = kb_addr + b_frag_off + (uint32_t)(np * 16 * AST + kk) * 2;
            LDMATRIX_X4(b[2 * np][0], b[2 * np][1], b[2 * np + 1][0], b[2 * np + 1][1], bb);
        }
        #pragma unroll
        for (int mi = 0; mi < 2; mi++)
            #pragma unroll
            for (int nt = 0; nt < 4; nt++)
                HMMA16816(sacc[mi][nt][0], sacc[mi][nt][1], sacc[mi][nt][2], sacc[mi][nt][3],
                          a[mi][0], a[mi][1], a[mi][2], a[mi][3],
                          b[nt][0], b[nt][1]);
    }
    __syncwarp();   // all q/k frag reads done before p (aliased to q) is written

    // ---- softmax per row (4 rows/thread), write fp16 P to smem ----
    const float scale = 0.125f;
    #pragma unroll
    for (int mi = 0; mi < 2; mi++) {
        #pragma unroll
        for (int half = 0; half < 2; half++) {
            int row = mi * 16 + gr + 8 * half;
            float e[8];
            float m = -1e30f;
            #pragma unroll
            for (int nt = 0; nt < 4; nt++) {
                e[2 * nt]     = sacc[mi][nt][2 * half]     * scale;
                e[2 * nt + 1] = sacc[mi][nt][2 * half + 1] * scale;
                m = fmaxf(m, fmaxf(e[2 * nt], e[2 * nt + 1]));
            }
            m = fmaxf(m, __shfl_xor_sync(0xFFFFFFFFu, m, 1));
            m = fmaxf(m, __shfl_xor_sync(0xFFFFFFFFu, m, 2));
            float sum = 0.f;
            #pragma unroll
            for (int j = 0; j < 8; j++) {
                e[j] = __expf(e[j] - m);
                sum += e[j];
            }
            sum += __shfl_xor_sync(0xFFFFFFFFu, sum, 1);
            sum += __shfl_xor_sync(0xFFFFFFFFu, sum, 2);
            float inv = __fdividef(1.0f, sum);
            #pragma unroll
            for (int nt = 0; nt < 4; nt++) {
                *(__half2*)&p[row * AST + nt * 8 + 2 * t] =
                    __floats2half2_rn(e[2 * nt] * inv, e[2 * nt + 1] * inv);
            }
        }
    }
    __syncwarp();

    // ---- O = P V : M=32, N=64, K=32 -> 2 ksteps of m16n8k16 ----
    float o[2][8][4];
    #pragma unroll
    for (int mi = 0; mi < 2; mi++)
        #pragma unroll
        for (int nt = 0; nt < 8; nt++)
            #pragma unroll
            for (int j = 0; j < 4; j++) o[mi][nt][j] = 0.f;

    #pragma unroll
    for (int kk = 0; kk < 32; kk += 16) {
        uint32_t a[2][4];
        #pragma unroll
        for (int mi = 0; mi < 2; mi++) {
            uint32_t aa = qb_addr + a_frag_off + (uint32_t)(mi * 16 * AST + kk) * 2;
            LDMATRIX_X4(a[mi][0], a[mi][1], a[mi][2], a[mi][3], aa);
        }
        #pragma unroll
        for (int nt = 0; nt < 8; nt++) {
            int n = nt * 8 + gr;
            // B-frag from V (tok=k, dim=n): pack halves (k=kk+2t, kk+2t+1) at col n
            uint32_t b0 = (uint32_t)vs[(kk + 2 * t) * AST + n] |
                          ((uint32_t)vs[(kk + 2 * t + 1) * AST + n] << 16);
            uint32_t b1 = (uint32_t)vs[(kk + 8 + 2 * t) * AST + n] |
                          ((uint32_t)vs[(kk + 8 + 2 * t + 1) * AST + n] << 16);
            #pragma unroll
            for (int mi = 0; mi < 2; mi++)
                HMMA16816(o[mi][nt][0], o[mi][nt][1], o[mi][nt][2], o[mi][nt][3],
                          a[mi][0], a[mi][1], a[mi][2], a[mi][3], b0, b1);
        }
    }

    // ---- store O fp16 to g_attn (T, C) ----
    __half* op = g_attn + (size_t)(w * WIN) * DIM + h * DH;
    #pragma unroll
    for (int mi = 0; mi < 2; mi++) {
        #pragma unroll
        for (int nt = 0; nt < 8; nt++) {
            int row0 = mi * 16 + gr;
            int col  = nt * 8 + 2 * t;
            *(__half2*)&op[(size_t)row0 * DIM + col] =
                __floats2half2_rn(o[mi][nt][0], o[mi][nt][1]);
            *(__half2*)&op[(size_t)(row0 + 8) * DIM + col] =
                __floats2half2_rn(o[mi][nt][2], o[mi][nt][3]);
        }
    }
}

// =================================================================================
// launch
// =================================================================================
extern "C" void kernel_launch(void* const* d_in, const int* in_sizes, int n_in,
                              void* d_out, int out_size)
{
    (void)in_sizes; (void)n_in; (void)out_size;
    const float* x     = (const float*)d_in[0];
    const float* w_qkv = (const float*)d_in[1];
    const float* w_out = (const float*)d_in[2];
    const float* gamma = (const float*)d_in[3];
    const float* beta  = (const float*)d_in[4];
    float* out = (float*)d_out;

    __half *normed, *qkv, *attn, *wqkv_h, *wout_h;
    cudaGetSymbolAddress((void**)&normed, g_normed);
    cudaGetSymbolAddress((void**)&qkv,    g_qkv);
    cudaGetSymbolAddress((void**)&attn,   g_attn);
    cudaGetSymbolAddress((void**)&wqkv_h, g_wqkv_h);
    cudaGetSymbolAddress((void**)&wout_h, g_wout_h);

    cudaFuncSetAttribute((const void*)hgemm_nt<false, __half>,
                         cudaFuncAttributeMaxDynamicSharedMemorySize, GSMEM_BYTES);
    cudaFuncSetAttribute((const void*)hgemm_nt<true, float>,
                         cudaFuncAttributeMaxDynamicSharedMemorySize, GSMEM_BYTES);
    cudaFuncSetAttribute((const void*)attn_mma_kernel,
                         cudaFuncAttributeMaxDynamicSharedMemorySize, ASMEM_BYTES);
    cudaFuncSetAttribute((const void*)ln_transpose_kernel,
                         cudaFuncAttributeMaxDynamicSharedMemorySize, LN_SMEM_BYTES);

    // 0) round weights to fp16; init RoPE table
    round_fp16_kernel<<<(QKV_N * DIM / 4 + 255) / 256, 256>>>(w_qkv, wqkv_h, QKV_N * DIM / 4);
    round_fp16_kernel<<<(DIM * DIM / 4 + 255) / 256, 256>>>(w_out, wout_h, DIM * DIM / 4);
    rope_init_kernel<<<1, 1024>>>();

    // 1) LayerNorm + transpose -> g_normed (T, C) fp16
    ln_transpose_kernel<<<TLEN / 32, dim3(32, 32), LN_SMEM_BYTES>>>(x, gamma, beta);

    // 2) QKV GEMM (fp16 mma.sync + ldmatrix, R8 config)
    hgemm_nt<false, __half><<<dim3(QKV_N / GBN, TLEN / GBM), 256, GSMEM_BYTES>>>(
        normed, wqkv_h, qkv, nullptr, TLEN, QKV_N, DIM);

    // 3) windowed RoPE attention (full fp16 mma) -> g_attn (T, C) fp16
    attn_mma_kernel<<<NWIN * HEADS / AWARPS, AWARPS * 32, ASMEM_BYTES>>>();

    // 4) out = (w_out @ attn^T) + x, written as (C, T) fp32
    hgemm_nt<true, float><<<dim3(TLEN / GBN, DIM / GBM), 256, GSMEM_BYTES>>>(
        wout_h, attn, out, x, DIM, TLEN, DIM);
}

// round 11
// speedup vs baseline: 1.1572x; 1.0480x over previous
#include <cuda_runtime.h>
#include <cuda_fp16.h>
#include <math.h>
#include <stdint.h>

#define DIM     1024
#define TLEN    16384
#define WIN     32
#define DH      64
#define HEADS   16
#define NWIN    (TLEN / WIN)      // 512
#define QKV_N   (3 * DIM)         // 3072

// ---------------- scratch (static device globals; no allocation) ----------------
static __device__ __half g_normed[(size_t)TLEN * DIM];   // (T, C) fp16
static __device__ __half g_qkv[(size_t)TLEN * QKV_N];    // (T, 3C) fp16
static __device__ __half g_attn[(size_t)TLEN * DIM];     // (T, C) fp16
static __device__ __half g_wqkv_h[(size_t)QKV_N * DIM];  // fp16 weights
static __device__ __half g_wout_h[(size_t)DIM * DIM];    // fp16 weights
static __device__ float  g_rope_cos[WIN * 32];
static __device__ float  g_rope_sin[WIN * 32];
static __device__ float  g_mean[TLEN];
static __device__ float  g_rstd[TLEN];

// =============================== helpers ===================================
__device__ __forceinline__ uint32_t smem_u32(const void* p) {
    uint32_t a;
    asm("{ .reg .u64 t; cvta.to.shared.u64 t, %1; cvt.u32.u64 %0, t; }" : "=r"(a) : "l"(p));
    return a;
}
#define LDMATRIX_X4(r0, r1, r2, r3, addr) \
    asm volatile("ldmatrix.sync.aligned.m8n8.x4.shared.b16 {%0,%1,%2,%3}, [%4];" \
                 : "=r"(r0), "=r"(r1), "=r"(r2), "=r"(r3) : "r"(addr))
#define HMMA16816(c0, c1, c2, c3, a0, a1, a2, a3, b0, b1) \
    asm volatile( \
        "mma.sync.aligned.m16n8k16.row.col.f32.f16.f16.f32 " \
        "{%0,%1,%2,%3},{%4,%5,%6,%7},{%8,%9},{%0,%1,%2,%3};" \
        : "+f"(c0), "+f"(c1), "+f"(c2), "+f"(c3) \
        : "r"(a0), "r"(a1), "r"(a2), "r"(a3), "r"(b0), "r"(b1))

// =================================================================================
// Kernel 0: preamble — round both weight matrices to fp16; last block inits RoPE
// =================================================================================
#define WQKV_Q (QKV_N * DIM / 4)      // 786432 quads
#define WOUT_Q (DIM * DIM / 4)        // 262144 quads
#define PRE_BLOCKS ((WQKV_Q + WOUT_Q + 255) / 256)   // 4096

__global__ void preamble_kernel(const float* __restrict__ w_qkv,
                                const float* __restrict__ w_out)
{
    if (blockIdx.x == PRE_BLOCKS) {
        // RoPE table init (1 block, 256 threads x 4)
        #pragma unroll
        for (int it = 0; it < 4; it++) {
            int idx = threadIdx.x + it * 256;    // 0..1023
            int n = idx >> 5;
            int i = idx & 31;
            float invf = expf(-logf(10000.f) * (float)i * (1.0f / 32.0f));
            float ang  = (float)n * invf;
            g_rope_cos[idx] = cosf(ang);
            g_rope_sin[idx] = sinf(ang);
        }
        return;
    }
    int i = blockIdx.x * blockDim.x + threadIdx.x;
    const float* in;
    __half* out;
    if (i < WQKV_Q) {
        in = w_qkv; out = g_wqkv_h;
    } else {
        i -= WQKV_Q;
        if (i >= WOUT_Q) return;
        in = w_out; out = g_wout_h;
    }
    float4 v = *(const float4*)&in[i * 4];
    *(__half2*)&out[i * 4]     = __floats2half2_rn(v.x, v.y);
    *(__half2*)&out[i * 4 + 2] = __floats2half2_rn(v.z, v.w);
}

// =================================================================================
// Kernel 1a: LN stats — per-token mean/rstd over channels. High occupancy.
// block = (64 tokens, 16 ch-lanes) = 1024 threads; grid = TLEN/64.
// =================================================================================
__global__ void __launch_bounds__(1024) ln_stats_kernel(const float* __restrict__ x)
{
    __shared__ float ssum[16][65];
    __shared__ float ssq[16][65];
    const int tx = threadIdx.x;      // token 0..63
    const int ty = threadIdx.y;      // lane 0..15
    const int t0 = blockIdx.x * 64;

    float sum = 0.f, sq = 0.f;
    #pragma unroll 8
    for (int c = ty; c < DIM; c += 16) {
        float v = x[(size_t)c * TLEN + t0 + tx];
        sum += v;
        sq  += v * v;
    }
    ssum[ty][tx] = sum;
    ssq[ty][tx]  = sq;
    __syncthreads();
    for (int s = 8; s > 0; s >>= 1) {
        if (ty < s) {
            ssum[ty][tx] += ssum[ty + s][tx];
            ssq[ty][tx]  += ssq[ty + s][tx];
        }
        __syncthreads();
    }
    if (ty == 0) {
        float m = ssum[0][tx] * (1.0f / DIM);
        float var = ssq[0][tx] * (1.0f / DIM) - m * m;
        g_mean[t0 + tx] = m;
        g_rstd[t0 + tx] = rsqrtf(var + 1e-5f);
    }
}

// =================================================================================
// Kernel 1b: LN apply + transpose (C,T)->(T,C) fp16. Re-reads x (L2-warm).
// block = (32,32); one smem staging tile; coalesced uint4 store phase.
// =================================================================================
#define LN_STRIDE 1026
#define LN_SMEM_BYTES (32 * LN_STRIDE * 2)   // 65664

__global__ void __launch_bounds__(1024) ln_apply_kernel(
    const float* __restrict__ x,
    const float* __restrict__ gamma,
    const float* __restrict__ beta)
{
    extern __shared__ __half st[];
    const int tx = threadIdx.x;      // token
    const int ty = threadIdx.y;      // channel lane
    const int t0 = blockIdx.x * 32;
    const int tid = ty * 32 + tx;

    const float mean = g_mean[t0 + tx];
    const float rstd = g_rstd[t0 + tx];

    #pragma unroll 8
    for (int ci = 0; ci < 32; ci++) {
        int c = ci * 32 + ty;
        float v = x[(size_t)c * TLEN + t0 + tx];
        float nv = (v - mean) * rstd * gamma[c] + beta[c];
        st[tx * LN_STRIDE + c] = __float2half_rn(nv);
    }
    __syncthreads();

    const uint32_t stb = smem_u32(st);
    #pragma unroll
    for (int i = 0; i < 4; i++) {
        int idx = tid + i * 1024;
        int tok = idx >> 7;
        int f4  = idx & 127;
        uint32_t sa = stb + (uint32_t)(tok * LN_STRIDE + f4 * 8) * 2;
        uint4 u;
        asm volatile("ld.shared.u32 %0, [%1];"      : "=r"(u.x) : "r"(sa));
        asm volatile("ld.shared.u32 %0, [%1 + 4];"  : "=r"(u.y) : "r"(sa));
        asm volatile("ld.shared.u32 %0, [%1 + 8];"  : "=r"(u.z) : "r"(sa));
        asm volatile("ld.shared.u32 %0, [%1 + 12];" : "=r"(u.w) : "r"(sa));
        *(uint4*)&g_normed[(size_t)(t0 + tok) * DIM + f4 * 8] = u;
    }
}

// =================================================================================
// Kernel 2: fp16 mma.sync GEMM-NT (R8/R10 config: 256 threads, 8 warps of 64x32).
// Chunk loop reordered: kstep0 MMAs before the cp.async prefetch burst.
// =================================================================================
#define GBM 128
#define GBN 128
#define GBK 64
#define GSTAGES 3
#define ROWH 72
#define TILEH (128 * ROWH)
#define STAGEH (2 * TILEH)
#define GSMEM_BYTES (GSTAGES * STAGEH * 2)   // 110592 B

template <bool RESID, typename TOUT>
__global__ void __launch_bounds__(256) hgemm_nt(
    const __half* __restrict__ A,
    const __half* __restrict__ B,
    TOUT* __restrict__ C,
    const float* __restrict__ resid,
    int M, int N, int K)
{
    extern __shared__ __half sh[];
    const uint32_t shb = smem_u32(sh);
    const int tid  = threadIdx.x;
    const int wid  = tid >> 5;
    const int lane = tid & 31;
    const int g = lane >> 2;
    const int t = lane & 3;
    const int m0 = blockIdx.y * GBM;
    const int n0 = blockIdx.x * GBN;
    const int wm = (wid >> 2) * 64;
    const int wn = (wid & 3) * 32;
    const int KC = K / GBK;

    const int a_row = wm + (lane & 15);
    const int a_col = (lane >> 4) << 3;
    const int b_row = wn + ((lane >> 4) << 3) + (lane & 7);
    const int b_col = ((lane >> 3) & 1) << 3;
    const uint32_t a_off = (uint32_t)(a_row * ROWH + a_col) * 2;
    const uint32_t b_off = (uint32_t)(TILEH + b_row * ROWH + b_col) * 2;

    float c[4][4][4];
    #pragma unroll
    for (int mi = 0; mi < 4; mi++)
        #pragma unroll
        for (int ni = 0; ni < 4; ni++)
            #pragma unroll
            for (int j = 0; j < 4; j++) c[mi][ni][j] = 0.f;

    const int lrow = tid >> 3;
    const int lc8  = (tid & 7) << 3;

    #pragma unroll
    for (int s = 0; s < GSTAGES - 1; s++) {
        __half* as = sh + s * STAGEH;
        __half* bs = as + TILEH;
        #pragma unroll
        for (int i = 0; i < 4; i++) {
            int row = lrow + i * 32;
            uint32_t sa = smem_u32(as + row * ROWH + lc8);
            const __half* ga = A + (size_t)(m0 + row) * K + s * GBK + lc8;
            asm volatile("cp.async.cg.shared.global [%0], [%1], 16;" :: "r"(sa), "l"(ga));
            uint32_t sb = smem_u32(bs + row * ROWH + lc8);
            const __half* gb = B + (size_t)(n0 + row) * K + s * GBK + lc8;
            asm volatile("cp.async.cg.shared.global [%0], [%1], 16;" :: "r"(sb), "l"(gb));
        }
        asm volatile("cp.async.commit_group;");
    }

#define GEMM_KSTEP(kk) do {                                                        \
        uint32_t a[4][4], b[4][2];                                                 \
        _Pragma("unroll")                                                          \
        for (int mi = 0; mi < 4; mi++) {                                           \
            uint32_t aa = abase + (uint32_t)(mi * 16 * ROWH + (kk)) * 2;           \
            LDMATRIX_X4(a[mi][0], a[mi][1], a[mi][2], a[mi][3], aa);               \
        }                                                                          \
        _Pragma("unroll")                                                          \
        for (int np = 0; np < 2; np++) {                                           \
            uint32_t bb = bbase + (uint32_t)(np * 16 * ROWH + (kk)) * 2;           \
            LDMATRIX_X4(b[2 * np][0], b[2 * np][1], b[2 * np + 1][0], b[2 * np + 1][1], bb); \
        }                                                                          \
        _Pragma("unroll")                                                          \
        for (int mi = 0; mi < 4; mi++)                                             \
            _Pragma("unroll")                                                      \
            for (int ni = 0; ni < 4; ni++)                                         \
                HMMA16816(c[mi][ni][0], c[mi][ni][1], c[mi][ni][2], c[mi][ni][3],  \
                          a[mi][0], a[mi][1], a[mi][2], a[mi][3],                  \
                          b[ni][0], b[ni][1]);                                     \
    } while (0)

    for (int kc = 0; kc < KC; kc++) {
        if (kc + 1 < KC) asm volatile("cp.async.wait_group 1;");
        else             asm volatile("cp.async.wait_group 0;");
        __syncthreads();

        const uint32_t stg = shb + (uint32_t)((kc % GSTAGES) * STAGEH) * 2;
        const uint32_t abase = stg + a_off;
        const uint32_t bbase = stg + b_off;

        // kstep 0 first: shortest barrier-to-MMA path
        GEMM_KSTEP(0);

        // prefetch chunk kc+2 into slot (kc+2)%3
        int nxt = kc + 2;
        if (nxt < KC) {
            int slot = nxt % GSTAGES;
            __half* as = sh + slot * STAGEH;
            __half* bs = as + TILEH;
            #pragma unroll
            for (int i = 0; i < 4; i++) {
                int row = lrow + i * 32;
                uint32_t sa = smem_u32(as + row * ROWH + lc8);
                const __half* ga = A + (size_t)(m0 + row) * K + nxt * GBK + lc8;
                asm volatile("cp.async.cg.shared.global [%0], [%1], 16;" :: "r"(sa), "l"(ga));
                uint32_t sb = smem_u32(bs + row * ROWH + lc8);
                const __half* gb = B + (size_t)(n0 + row) * K + nxt * GBK + lc8;
                asm volatile("cp.async.cg.shared.global [%0], [%1], 16;" :: "r"(sb), "l"(gb));
            }
            asm volatile("cp.async.commit_group;");
        }

        GEMM_KSTEP(16);
        GEMM_KSTEP(32);
        GEMM_KSTEP(48);
    }
#undef GEMM_KSTEP

    #pragma unroll
    for (int mi = 0; mi < 4; mi++) {
        #pragma unroll
        for (int ni = 0; ni < 4; ni++) {
            size_t r0  = (size_t)(m0 + wm + mi * 16 + g);
            size_t col = (size_t)(n0 + wn + ni * 8 + 2 * t);
            size_t off0 = r0 * N + col;
            size_t off1 = (r0 + 8) * N + col;
            if constexpr (RESID) {
                float2 rv0 = *(const float2*)&resid[off0];
                float2 rv1 = *(const float2*)&resid[off1];
                float2 v0 = make_float2(c[mi][ni][0] + rv0.x, c[mi][ni][1] + rv0.y);
                float2 v1 = make_float2(c[mi][ni][2] + rv1.x, c[mi][ni][3] + rv1.y);
                *(float2*)&((float*)C)[off0] = v0;
                *(float2*)&((float*)C)[off1] = v1;
            } else {
                *(__half2*)&((__half*)C)[off0] = __floats2half2_rn(c[mi][ni][0], c[mi][ni][1]);
                *(__half2*)&((__half*)C)[off1] = __floats2half2_rn(c[mi][ni][2], c[mi][ni][3]);
            }
        }
    }
}

// =================================================================================
// Kernel 3: warp-per-(window,head) attention, full fp16 (m16n8k16), fp32 accum.
// =================================================================================
#define AWARPS 4
#define AST 72
#define AWARP_H (3 * 32 * AST)
#define ASMEM_BYTES (AWARPS * AWARP_H * 2)       // 55296 B

__global__ void __launch_bounds__(AWARPS * 32) attn_mma_kernel()
{
    extern __shared__ __half ash[];
    const int lane = threadIdx.x & 31;
    const int wid  = threadIdx.x >> 5;
    const int pair = blockIdx.x * AWARPS + wid;
    const int w = pair >> 4;
    const int h = pair & 15;
    const int gr = lane >> 2;
    const int t  = lane & 3;

    __half* q = ash + wid * AWARP_H;
    __half* k = q + 32 * AST;
    __half* v = k + 32 * AST;
    __half* p = q;

    const uint32_t qb_addr = smem_u32(q);
    const uint32_t kb_addr = smem_u32(k);
    const unsigned short* vs = (const unsigned short*)v;

    const __half* gbase = g_qkv + (size_t)w * WIN * QKV_N + h * DH;

    #pragma unroll
    for (int it = 0; it < 8; it++) {
        int idx = lane + it * 32;
        int n   = idx >> 3;
        int d8  = (idx & 7) << 3;
        const __half* rp = gbase + (size_t)n * QKV_N + d8;
        *(uint4*)&q[n * AST + d8] = *(const uint4*)rp;
        *(uint4*)&k[n * AST + d8] = *(const uint4*)(rp + DIM);
        *(uint4*)&v[n * AST + d8] = *(const uint4*)(rp + 2 * DIM);
    }
    __syncwarp();

    #pragma unroll
    for (int it = 0; it < 32; it++) {
        int idx = lane + it * 32;
        int n = idx >> 5;
        int i = idx & 31;
        float c = g_rope_cos[idx];
        float s = g_rope_sin[idx];
        __half* qr = q + n * AST;
        __half* kr = k + n * AST;
        float qa = __half2float(qr[i]), qb = __half2float(qr[i + 32]);
        qr[i]      = __float2half_rn(qa * c - qb * s);
        qr[i + 32] = __float2half_rn(qb * c + qa * s);
        float ka = __half2float(kr[i]), kb = __half2float(kr[i + 32]);
        kr[i]      = __float2half_rn(ka * c - kb * s);
        kr[i + 32] = __float2half_rn(kb * c + ka * s);
    }
    __syncwarp();

    const uint32_t a_frag_off = (uint32_t)((lane & 15) * AST + ((lane >> 4) << 3)) * 2;
    const uint32_t b_frag_off = (uint32_t)((((lane >> 4) << 3) + (lane & 7)) * AST +
                                           (((lane >> 3) & 1) << 3)) * 2;

    float sacc[2][4][4];
    #pragma unroll
    for (int mi = 0; mi < 2; mi++)
        #pragma unroll
        for (int nt = 0; nt < 4; nt++)
            #pragma unroll
            for (int j = 0; j < 4; j++) sacc[mi][nt][j] = 0.f;

    #pragma unroll
    for (int kk = 0; kk < 64; kk += 16) {
        uint32_t a[2][4], b[4][2];
        #pragma unroll
        for (int mi = 0; mi < 2; mi++) {
            uint32_t aa = qb_addr + a_frag_off + (uint32_t)(mi * 16 * AST + kk) * 2;
            LDMATRIX_X4(a[mi][0], a[mi][1], a[mi][2], a[mi][3], aa);
        }
        #pragma unroll
        for (int np = 0; np < 2; np++) {
            uint32_t bb = kb_addr + b_frag_off + (uint32_t)(np * 16 * AST + kk) * 2;
            LDMATRIX_X4(b[2 * np][0], b[2 * np][1], b[2 * np + 1][0], b[2 * np + 1][1], bb);
        }
        #pragma unroll
        for (int mi = 0; mi < 2; mi++)
            #pragma unroll
            for (int nt = 0; nt < 4; nt++)
                HMMA16816(sacc[mi][nt][0], sacc[mi][nt][1], sacc[mi][nt][2], sacc[mi][nt][3],
                          a[mi][0], a[mi][1], a[mi][2], a[mi][3],
                          b[nt][0], b[nt][1]);
    }
    __syncwarp();

    const float scale = 0.125f;
    #pragma unroll
    for (int mi = 0; mi < 2; mi++) {
        #pragma unroll
        for (int half = 0; half < 2; half++) {
            int row = mi * 16 + gr + 8 * half;
            float e[8];
            float m = -1e30f;
            #pragma unroll
            for (int nt = 0; nt < 4; nt++) {
                e[2 * nt]     = sacc[mi][nt][2 * half]     * scale;
                e[2 * nt + 1] = sacc[mi][nt][2 * half + 1] * scale;
                m = fmaxf(m, fmaxf(e[2 * nt], e[2 * nt + 1]));
            }
            m = fmaxf(m, __shfl_xor_sync(0xFFFFFFFFu, m, 1));
            m = fmaxf(m, __shfl_xor_sync(0xFFFFFFFFu, m, 2));
            float sum = 0.f;
            #pragma unroll
            for (int j = 0; j < 8; j++) {
                e[j] = __expf(e[j] - m);
                sum += e[j];
            }
            sum += __shfl_xor_sync(0xFFFFFFFFu, sum, 1);
            sum += __shfl_xor_sync(0xFFFFFFFFu, sum, 2);
            float inv = __fdividef(1.0f, sum);
            #pragma unroll
            for (int nt = 0; nt < 4; nt++) {
                *(__half2*)&p[row * AST + nt * 8 + 2 * t] =
                    __floats2half2_rn(e[2 * nt] * inv, e[2 * nt + 1] * inv);
            }
        }
    }
    __syncwarp();

    float o[2][8][4];
    #pragma unroll
    for (int mi = 0; mi < 2; mi++)
        #pragma unroll
        for (int nt = 0; nt < 8; nt++)
            #pragma unroll
            for (int j = 0; j < 4; j++) o[mi][nt][j] = 0.f;

    #pragma unroll
    for (int kk = 0; kk < 32; kk += 16) {
        uint32_t a[2][4];
        #pragma unroll
        for (int mi = 0; mi < 2; mi++) {
            uint32_t aa = qb_addr + a_frag_off + (uint32_t)(mi * 16 * AST + kk) * 2;
            LDMATRIX_X4(a[mi][0], a[mi][1], a[mi][2], a[mi][3], aa);
        }
        #pragma unroll
        for (int nt = 0; nt < 8; nt++) {
            int n = nt * 8 + gr;
            uint32_t b0 = (uint32_t)vs[(kk + 2 * t) * AST + n] |
                          ((uint32_t)vs[(kk + 2 * t + 1) * AST + n] << 16);
            uint32_t b1 = (uint32_t)vs[(kk + 8 + 2 * t) * AST + n] |
                          ((uint32_t)vs[(kk + 8 + 2 * t + 1) * AST + n] << 16);
            #pragma unroll
            for (int mi = 0; mi < 2; mi++)
                HMMA16816(o[mi][nt][0], o[mi][nt][1], o[mi][nt][2], o[mi][nt][3],
                          a[mi][0], a[mi][1], a[mi][2], a[mi][3], b0, b1);
        }
    }

    __half* op = g_attn + (size_t)(w * WIN) * DIM + h * DH;
    #pragma unroll
    for (int mi = 0; mi < 2; mi++) {
        #pragma unroll
        for (int nt = 0; nt < 8; nt++) {
            int row0 = mi * 16 + gr;
            int col  = nt * 8 + 2 * t;
            *(__half2*)&op[(size_t)row0 * DIM + col] =
                __floats2half2_rn(o[mi][nt][0], o[mi][nt][1]);
            *(__half2*)&op[(size_t)(row0 + 8) * DIM + col] =
                __floats2half2_rn(o[mi][nt][2], o[mi][nt][3]);
        }
    }
}

// =================================================================================
// launch
// =================================================================================
extern "C" void kernel_launch(void* const* d_in, const int* in_sizes, int n_in,
                              void* d_out, int out_size)
{
    (void)in_sizes; (void)n_in; (void)out_size;
    const float* x     = (const float*)d_in[0];
    const float* w_qkv = (const float*)d_in[1];
    const float* w_out = (const float*)d_in[2];
    const float* gamma = (const float*)d_in[3];
    const float* beta  = (const float*)d_in[4];
    float* out = (float*)d_out;

    __half *normed, *qkv, *attn, *wqkv_h, *wout_h;
    cudaGetSymbolAddress((void**)&normed, g_normed);
    cudaGetSymbolAddress((void**)&qkv,    g_qkv);
    cudaGetSymbolAddress((void**)&attn,   g_attn);
    cudaGetSymbolAddress((void**)&wqkv_h, g_wqkv_h);
    cudaGetSymbolAddress((void**)&wout_h, g_wout_h);

    cudaFuncSetAttribute((const void*)hgemm_nt<false, __half>,
                         cudaFuncAttributeMaxDynamicSharedMemorySize, GSMEM_BYTES);
    cudaFuncSetAttribute((const void*)hgemm_nt<true, float>,
                         cudaFuncAttributeMaxDynamicSharedMemorySize, GSMEM_BYTES);
    cudaFuncSetAttribute((const void*)attn_mma_kernel,
                         cudaFuncAttributeMaxDynamicSharedMemorySize, ASMEM_BYTES);
    cudaFuncSetAttribute((const void*)ln_apply_kernel,
                         cudaFuncAttributeMaxDynamicSharedMemorySize, LN_SMEM_BYTES);

    // 0) preamble: round weights + RoPE table (one launch)
    preamble_kernel<<<PRE_BLOCKS + 1, 256>>>(w_qkv, w_out);

    // 1) LayerNorm: stats, then apply+transpose -> g_normed (T, C) fp16
    ln_stats_kernel<<<TLEN / 64, dim3(64, 16)>>>(x);
    ln_apply_kernel<<<TLEN / 32, dim3(32, 32), LN_SMEM_BYTES>>>(x, gamma, beta);

    // 2) QKV GEMM (fp16 mma.sync + ldmatrix)
    hgemm_nt<false, __half><<<dim3(QKV_N / GBN, TLEN / GBM), 256, GSMEM_BYTES>>>(
        normed, wqkv_h, qkv, nullptr, TLEN, QKV_N, DIM);

    // 3) windowed RoPE attention (full fp16 mma) -> g_attn (T, C) fp16
    attn_mma_kernel<<<NWIN * HEADS / AWARPS, AWARPS * 32, ASMEM_BYTES>>>();

    // 4) out = (w_out @ attn^T) + x, written as (C, T) fp32
    hgemm_nt<true, float><<<dim3(TLEN / GBN, DIM / GBM), 256, GSMEM_BYTES>>>(
        wout_h, attn, out, x, DIM, TLEN, DIM);
}